// round 1
// baseline (speedup 1.0000x reference)
#include <cuda_runtime.h>
#include <math.h>
#include <stdint.h>

// ---------------- compile-time maxima (problem shapes are fixed) -------------
#define MAXN 10000
#define MAXE 50000
#define MAXB 512
#define H 64
#define HH 4096      // H*H
#define WID 128      // edge-MLP hidden width
#define GRU3 192     // 3*H
#define LST4 256     // 4*H

// ---------------- device scratch (allocation-free rule: __device__ globals) --
__device__ float g_Wedge[(size_t)MAXE * HH];   // 819.2 MB edge weight matrices
__device__ float g_hid[(size_t)MAXE * WID];    // edge MLP hidden [E,128]
__device__ float g_x[MAXN * H];                // node state (x == h for GRU)
__device__ float g_agg[MAXN * H];              // message aggregation
__device__ float g_deg[MAXN];
__device__ float g_e[MAXN];                    // attention scores
__device__ float g_hl[MAXB * H];
__device__ float g_cl[MAXB * H];
__device__ float g_qstar[MAXB * 2 * H];
__device__ int   g_segptr[MAXB + 1];
// transposed weights (for coalesced matvec reads)
__device__ float g_rootWT[H * H];          // [i][o]
__device__ float g_gruWihT[H * GRU3];      // [i][row]
__device__ float g_gruWhhT[H * GRU3];
__device__ float g_lstmWihT[2 * H * LST4]; // [i][row]
__device__ float g_lstmWhhT[H * LST4];

__device__ __forceinline__ float sigm(float v) { return 1.f / (1.f + expf(-v)); }
__device__ __forceinline__ float siluf(float v) { return v / (1.f + expf(-v)); }

// ---------------- zero fills -------------------------------------------------
__global__ void k_zero_deg(int N) {
    int i = blockIdx.x * blockDim.x + threadIdx.x;
    if (i < N) g_deg[i] = 0.f;
}
__global__ void k_zero_agg(int n) {
    int i = blockIdx.x * blockDim.x + threadIdx.x;
    if (i < n) g_agg[i] = 0.f;
}
__global__ void k_zero_readout(int B) {
    int i = blockIdx.x * blockDim.x + threadIdx.x;
    if (i < B * H) { g_hl[i] = 0.f; g_cl[i] = 0.f; }
    if (i < B * 2 * H) g_qstar[i] = 0.f;
}

// ---------------- weight transposes -----------------------------------------
__global__ void k_transpose_all(const float* __restrict__ rootW,
                                const float* __restrict__ gWih,
                                const float* __restrict__ gWhh,
                                const float* __restrict__ lWih,
                                const float* __restrict__ lWhh) {
    int i = blockIdx.x * blockDim.x + threadIdx.x;
    if (i < H * H)        { int r = i >> 6, c = i & 63;  g_rootWT[c * H + r]      = rootW[i]; }
    if (i < GRU3 * H)     { int r = i / H,  c = i % H;   g_gruWihT[c * GRU3 + r]  = gWih[i]; }
    if (i < GRU3 * H)     { int r = i / H,  c = i % H;   g_gruWhhT[c * GRU3 + r]  = gWhh[i]; }
    if (i < LST4 * 2 * H) { int r = i >> 7, c = i & 127; g_lstmWihT[c * LST4 + r] = lWih[i]; }
    if (i < LST4 * H)     { int r = i >> 6, c = i & 63;  g_lstmWhhT[c * LST4 + r] = lWhh[i]; }
}

// ---------------- node embedding: x = silu(x @ fl_W^T + fl_b) ----------------
__global__ void k_node_embed(const float* __restrict__ x, const float* __restrict__ W,
                             const float* __restrict__ b, int N) {
    int sub = threadIdx.x >> 6, o = threadIdx.x & 63;
    int n = blockIdx.x * 4 + sub;
    __shared__ float xs[4][11];
    bool ok = n < N;
    if (ok && o < 11) xs[sub][o] = x[n * 11 + o];
    __syncthreads();
    if (ok) {
        float a = b[o];
        #pragma unroll
        for (int i = 0; i < 11; i++) a += xs[sub][i] * W[o * 11 + i];
        g_x[n * H + o] = siluf(a);
    }
}

// ---------------- edge MLP hidden + degree -----------------------------------
__global__ void k_edge_hidden(const int* __restrict__ ei, const float* __restrict__ ea,
                              const float* __restrict__ pos, const float* __restrict__ W1,
                              const float* __restrict__ b1, int E) {
    int e = blockIdx.x, t = threadIdx.x;  // 128 threads
    __shared__ float ef[5];
    if (t < 4) ef[t] = ea[e * 4 + t];
    if (t == 4) {
        int s = ei[e], d = ei[E + e];
        float dx = pos[s * 3 + 0] - pos[d * 3 + 0];
        float dy = pos[s * 3 + 1] - pos[d * 3 + 1];
        float dz = pos[s * 3 + 2] - pos[d * 3 + 2];
        ef[4] = sqrtf(dx * dx + dy * dy + dz * dz);
    }
    if (t == 5) { int d = ei[E + e]; atomicAdd(&g_deg[d], 1.f); }
    __syncthreads();
    float a = b1[t];
    #pragma unroll
    for (int i = 0; i < 5; i++) a += ef[i] * W1[t * 5 + i];
    g_hid[(size_t)e * WID + t] = siluf(a);
}

// ---------------- big GEMM: W_edge = g_hid[E,128] @ nn_W2^T[128,4096] + b2 ---
// Tiles: BM=128 edges x BN=64 outputs, full K=128 in smem. 8x4 register tile.
__global__ __launch_bounds__(256, 2) void k_wedge(const float* __restrict__ Bm,
                                                  const float* __restrict__ bias, int E) {
    extern __shared__ float smem[];
    float* As = smem;               // [k][e] 128x128
    float* Bs = smem + 128 * 128;   // [k][j] 128x64
    int e0 = blockIdx.x * 128;
    int j0 = blockIdx.y * 64;
    int tid = threadIdx.x;
    // load A tile (transpose to k-major)
    {
        int r = tid >> 1;
        int kb = (tid & 1) * 64;
        int e = e0 + r;
        const float4* src = (const float4*)(g_hid + (size_t)e * WID + kb);
        #pragma unroll
        for (int q = 0; q < 16; q++) {
            float4 v = (e < E) ? src[q] : make_float4(0.f, 0.f, 0.f, 0.f);
            int k = kb + q * 4;
            As[(k + 0) * 128 + r] = v.x; As[(k + 1) * 128 + r] = v.y;
            As[(k + 2) * 128 + r] = v.z; As[(k + 3) * 128 + r] = v.w;
        }
    }
    // load B tile (transpose to k-major)
    {
        int r = tid >> 2;
        int kb = (tid & 3) * 32;
        const float4* src = (const float4*)(Bm + (size_t)(j0 + r) * WID + kb);
        #pragma unroll
        for (int q = 0; q < 8; q++) {
            float4 v = src[q];
            int k = kb + q * 4;
            Bs[(k + 0) * 64 + r] = v.x; Bs[(k + 1) * 64 + r] = v.y;
            Bs[(k + 2) * 64 + r] = v.z; Bs[(k + 3) * 64 + r] = v.w;
        }
    }
    __syncthreads();
    int tx = tid & 15, ty = tid >> 4;
    float acc[8][4];
    #pragma unroll
    for (int i = 0; i < 8; i++)
        #pragma unroll
        for (int j = 0; j < 4; j++) acc[i][j] = 0.f;
    #pragma unroll 8
    for (int k = 0; k < 128; k++) {
        float4 a0 = *(const float4*)&As[k * 128 + tx * 4];
        float4 a1 = *(const float4*)&As[k * 128 + 64 + tx * 4];
        float4 bv = *(const float4*)&Bs[k * 64 + ty * 4];
        float a[8] = {a0.x, a0.y, a0.z, a0.w, a1.x, a1.y, a1.z, a1.w};
        #pragma unroll
        for (int i = 0; i < 8; i++) {
            acc[i][0] += a[i] * bv.x; acc[i][1] += a[i] * bv.y;
            acc[i][2] += a[i] * bv.z; acc[i][3] += a[i] * bv.w;
        }
    }
    float4 bb = *(const float4*)&bias[j0 + ty * 4];
    #pragma unroll
    for (int i = 0; i < 8; i++) {
        int e = e0 + ((i < 4) ? (tx * 4 + i) : (64 + tx * 4 + i - 4));
        if (e < E) {
            float4 v = make_float4(acc[i][0] + bb.x, acc[i][1] + bb.y,
                                   acc[i][2] + bb.z, acc[i][3] + bb.w);
            *(float4*)&g_Wedge[(size_t)e * HH + j0 + ty * 4] = v;
        }
    }
}

// ---------------- message pass: agg[dst] += x[src] @ W_e ---------------------
__global__ void k_message(const int* __restrict__ ei, int E) {
    int sub = threadIdx.x >> 6, o = threadIdx.x & 63;
    int e = blockIdx.x * 4 + sub;
    __shared__ float xs[4][H];
    bool ok = e < E;
    int d = 0;
    if (ok) {
        int s = ei[e]; d = ei[E + e];
        xs[sub][o] = g_x[s * H + o];
    }
    __syncthreads();
    if (ok) {
        const float* W = g_Wedge + (size_t)e * HH;
        float m = 0.f;
        #pragma unroll
        for (int i = 0; i < H; i++) m += xs[sub][i] * W[i * H + o];
        atomicAdd(&g_agg[d * H + o], m);
    }
}

// ---------------- combine (root linear + agg/deg, silu) + GRU cell -----------
__global__ void k_combine_gru(const float* __restrict__ rb, const float* __restrict__ bih,
                              const float* __restrict__ bhh, int N) {
    int sub = threadIdx.x >> 6, o = threadIdx.x & 63;
    int n = blockIdx.x * 4 + sub;
    __shared__ float xs[4][H], xcs[4][H];
    bool ok = n < N;
    float xo = 0.f;
    if (ok) { xo = g_x[n * H + o]; xs[sub][o] = xo; }
    __syncthreads();
    if (ok) {
        float dg = g_deg[n]; if (dg < 1.f) dg = 1.f;
        float a = rb[o] + g_agg[n * H + o] / dg;
        #pragma unroll 8
        for (int i = 0; i < H; i++) a += xs[sub][i] * g_rootWT[i * H + o];
        xcs[sub][o] = siluf(a);
    }
    __syncthreads();
    if (ok) {
        float gi0 = bih[o], gi1 = bih[64 + o], gi2 = bih[128 + o];
        float gh0 = bhh[o], gh1 = bhh[64 + o], gh2 = bhh[128 + o];
        #pragma unroll 4
        for (int i = 0; i < H; i++) {
            float xi = xcs[sub][i], hi = xs[sub][i];
            const float* wi = &g_gruWihT[i * GRU3];
            const float* wh = &g_gruWhhT[i * GRU3];
            gi0 += xi * wi[o];      gh0 += hi * wh[o];
            gi1 += xi * wi[64 + o]; gh1 += hi * wh[64 + o];
            gi2 += xi * wi[128 + o]; gh2 += hi * wh[128 + o];
        }
        float r = sigm(gi0 + gh0);
        float z = sigm(gi1 + gh1);
        float nn = tanhf(gi2 + r * gh2);
        g_x[n * H + o] = (1.f - z) * nn + z * xo;
    }
}

// ---------------- Set2Set ----------------------------------------------------
__global__ void k_segptr(const int* __restrict__ batch, int N, int B) {
    int b = blockIdx.x * blockDim.x + threadIdx.x;
    if (b > B) return;
    int lo = 0, hi = N;
    while (lo < hi) { int m = (lo + hi) >> 1; if (batch[m] < b) lo = m + 1; else hi = m; }
    g_segptr[b] = lo;
}

__global__ void k_lstm(const float* __restrict__ bih, const float* __restrict__ bhh) {
    int b = blockIdx.x, t = threadIdx.x;  // 256 threads, one gate row each
    __shared__ float qs[2 * H], hs[H], gs[LST4];
    if (t < 2 * H) qs[t] = g_qstar[b * 2 * H + t];
    if (t < H) hs[t] = g_hl[b * H + t];
    __syncthreads();
    float g = bih[t] + bhh[t];
    #pragma unroll 8
    for (int i = 0; i < 2 * H; i++) g += qs[i] * g_lstmWihT[i * LST4 + t];
    #pragma unroll 8
    for (int i = 0; i < H; i++) g += hs[i] * g_lstmWhhT[i * LST4 + t];
    gs[t] = g;
    __syncthreads();
    if (t < H) {
        float ig = sigm(gs[t]), fg = sigm(gs[64 + t]);
        float gg = tanhf(gs[128 + t]), og = sigm(gs[192 + t]);
        float c = fg * g_cl[b * H + t] + ig * gg;
        g_cl[b * H + t] = c;
        g_hl[b * H + t] = og * tanhf(c);
    }
}

__global__ void k_escore(const int* __restrict__ batch, int N) {
    int gw = (blockIdx.x * blockDim.x + threadIdx.x) >> 5;
    int lane = threadIdx.x & 31;
    if (gw >= N) return;
    int b = batch[gw];
    float v = g_x[gw * H + lane] * g_hl[b * H + lane]
            + g_x[gw * H + 32 + lane] * g_hl[b * H + 32 + lane];
    #pragma unroll
    for (int off = 16; off; off >>= 1) v += __shfl_xor_sync(0xffffffffu, v, off);
    if (lane == 0) g_e[gw] = v;
}

__global__ void k_attend(int B) {
    int b = blockIdx.x, t = threadIdx.x;  // 64 threads
    __shared__ float red[H];
    int s = g_segptr[b], en = g_segptr[b + 1];
    float mx = -3.4e38f;
    for (int n = s + t; n < en; n += H) mx = fmaxf(mx, g_e[n]);
    red[t] = mx; __syncthreads();
    for (int off = 32; off; off >>= 1) { if (t < off) red[t] = fmaxf(red[t], red[t + off]); __syncthreads(); }
    float mxv = red[0];
    __syncthreads();
    float sm = 0.f;
    for (int n = s + t; n < en; n += H) sm += expf(g_e[n] - mxv);
    red[t] = sm; __syncthreads();
    for (int off = 32; off; off >>= 1) { if (t < off) red[t] += red[t + off]; __syncthreads(); }
    float den = red[0];
    float r = 0.f;
    for (int n = s; n < en; n++) r += expf(g_e[n] - mxv) * g_x[n * H + t];
    r = (en > s) ? r / den : 0.f;
    g_qstar[b * 2 * H + t] = g_hl[b * H + t];
    g_qstar[b * 2 * H + H + t] = r;
}

__global__ void k_out(const float* __restrict__ W1, const float* __restrict__ b1,
                      const float* __restrict__ W2, const float* __restrict__ b2,
                      float* __restrict__ out) {
    int b = blockIdx.x, t = threadIdx.x;  // 64 threads
    __shared__ float qs[2 * H];
    __shared__ float red[H];
    qs[t] = g_qstar[b * 2 * H + t];
    qs[64 + t] = g_qstar[b * 2 * H + 64 + t];
    __syncthreads();
    float a = b1[t];
    #pragma unroll 8
    for (int i = 0; i < 2 * H; i++) a += qs[i] * W1[t * 2 * H + i];
    red[t] = siluf(a) * W2[t];
    __syncthreads();
    for (int off = 32; off; off >>= 1) { if (t < off) red[t] += red[t + off]; __syncthreads(); }
    if (t == 0) out[b] = red[0] + b2[0];
}

// ---------------- host launcher ----------------------------------------------
extern "C" void kernel_launch(void* const* d_in, const int* in_sizes, int n_in,
                              void* d_out, int out_size) {
    const float* x = (const float*)d_in[0];
    int N = in_sizes[0] / 11;
    // disambiguate input ordering: dict order has pos at slot 2 (size 3N)
    bool dictOrder = (in_sizes[2] == 3 * N);
    const int*   ei  = (const int*)  d_in[dictOrder ? 3 : 1];
    const float* ea  = (const float*)d_in[dictOrder ? 1 : 2];
    const float* pos = (const float*)d_in[dictOrder ? 2 : 3];
    const int*   batch = (const int*)d_in[4];
    int E = in_sizes[dictOrder ? 3 : 1] / 2;
    int B = out_size;

    const float* fl_W  = (const float*)d_in[5];
    const float* fl_b  = (const float*)d_in[6];
    const float* nn_W1 = (const float*)d_in[7];
    const float* nn_b1 = (const float*)d_in[8];
    const float* nn_W2 = (const float*)d_in[9];
    const float* nn_b2 = (const float*)d_in[10];
    const float* root_W = (const float*)d_in[11];
    const float* root_b = (const float*)d_in[12];
    const float* gru_Wih = (const float*)d_in[13];
    const float* gru_Whh = (const float*)d_in[14];
    const float* gru_bih = (const float*)d_in[15];
    const float* gru_bhh = (const float*)d_in[16];
    const float* lstm_Wih = (const float*)d_in[17];
    const float* lstm_Whh = (const float*)d_in[18];
    const float* lstm_bih = (const float*)d_in[19];
    const float* lstm_bhh = (const float*)d_in[20];
    const float* out_W1 = (const float*)d_in[21];
    const float* out_b1 = (const float*)d_in[22];
    const float* out_W2 = (const float*)d_in[23];
    const float* out_b2 = (const float*)d_in[24];
    float* out = (float*)d_out;

    cudaFuncSetAttribute(k_wedge, cudaFuncAttributeMaxDynamicSharedMemorySize, 96 * 1024);

    k_zero_deg<<<(N + 255) / 256, 256>>>(N);
    k_node_embed<<<(N + 3) / 4, 256>>>(x, fl_W, fl_b, N);
    k_edge_hidden<<<E, 128>>>(ei, ea, pos, nn_W1, nn_b1, E);
    k_transpose_all<<<128, 256>>>(root_W, gru_Wih, gru_Whh, lstm_Wih, lstm_Whh);

    dim3 gw((E + 127) / 128, HH / 64);
    k_wedge<<<gw, 256, 96 * 1024>>>(nn_W2, nn_b2, E);

    for (int l = 0; l < 4; l++) {
        k_zero_agg<<<(N * H + 255) / 256, 256>>>(N * H);
        k_message<<<(E + 3) / 4, 256>>>(ei, E);
        k_combine_gru<<<(N + 3) / 4, 256>>>(root_b, gru_bih, gru_bhh, N);
    }

    k_zero_readout<<<(B * 2 * H + 255) / 256, 256>>>(B);
    k_segptr<<<(B + 1 + 255) / 256, 256>>>(batch, N, B);
    for (int s = 0; s < 3; s++) {
        k_lstm<<<B, 256>>>(lstm_bih, lstm_bhh);
        k_escore<<<(N * 32 + 255) / 256, 256>>>(batch, N);
        k_attend<<<B, 64>>>(B);
    }
    k_out<<<B, 64>>>(out_W1, out_b1, out_W2, out_b2, out);
}

// round 3
// speedup vs baseline: 2.1099x; 2.1099x over previous
#include <cuda_runtime.h>
#include <cuda_fp16.h>
#include <cuda_bf16.h>
#include <math.h>
#include <stdint.h>

// ---------------- compile-time maxima (problem shapes are fixed) -------------
#define MAXN 10000
#define MAXE 50000
#define MAXB 512
#define H 64
#define HH 4096      // H*H
#define WID 128      // edge-MLP hidden width
#define GRU3 192     // 3*H
#define LST4 256     // 4*H

// ---------------- device scratch (allocation-free rule: __device__ globals) --
__device__ __half g_WedgeH[(size_t)MAXE * HH];          // 409.6 MB fp16 edge weights
__device__ __nv_bfloat16 g_hidhi[(size_t)(MAXE + 128) * WID];
__device__ __nv_bfloat16 g_hidlo[(size_t)(MAXE + 128) * WID];
__device__ __nv_bfloat16 g_W2hi[HH * WID];
__device__ __nv_bfloat16 g_W2lo[HH * WID];
__device__ float g_x[MAXN * H];
__device__ float g_agg[MAXN * H];
__device__ float g_deg[MAXN];
__device__ float g_e[MAXN];
__device__ float g_hl[MAXB * H];
__device__ float g_cl[MAXB * H];
__device__ float g_qstar[MAXB * 2 * H];
__device__ int   g_segptr[MAXB + 1];
__device__ float g_rootWT[H * H];
__device__ float g_gruWihT[H * GRU3];
__device__ float g_gruWhhT[H * GRU3];
__device__ float g_lstmWihT[2 * H * LST4];
__device__ float g_lstmWhhT[H * LST4];

__device__ __forceinline__ float sigm(float v) { return 1.f / (1.f + expf(-v)); }
__device__ __forceinline__ float siluf(float v) { return v / (1.f + expf(-v)); }

__device__ __forceinline__ uint32_t smem_to_u32(const void* p) {
    uint32_t a;
    asm("{ .reg .u64 t; cvta.to.shared.u64 t, %1; cvt.u32.u64 %0, t; }" : "=r"(a) : "l"(p));
    return a;
}

// ---------------- mma.sync helpers -------------------------------------------
#define LDSM_X4(r, addr) \
    asm volatile("ldmatrix.sync.aligned.m8n8.x4.shared.b16 {%0,%1,%2,%3}, [%4];" \
        : "=r"((r)[0]), "=r"((r)[1]), "=r"((r)[2]), "=r"((r)[3]) : "r"(addr))
#define LDSM_X2(r, addr) \
    asm volatile("ldmatrix.sync.aligned.m8n8.x2.shared.b16 {%0,%1}, [%2];" \
        : "=r"((r)[0]), "=r"((r)[1]) : "r"(addr))
#define MMA_BF16(c, a, b) \
    asm volatile("mma.sync.aligned.m16n8k16.row.col.f32.bf16.bf16.f32 " \
        "{%0,%1,%2,%3}, {%4,%5,%6,%7}, {%8,%9}, {%0,%1,%2,%3};" \
        : "+f"((c)[0]), "+f"((c)[1]), "+f"((c)[2]), "+f"((c)[3]) \
        : "r"((a)[0]), "r"((a)[1]), "r"((a)[2]), "r"((a)[3]), "r"((b)[0]), "r"((b)[1]))
#define CP_ASYNC16(s, g) \
    asm volatile("cp.async.cg.shared.global [%0], [%1], 16;" :: "r"(s), "l"(g))
#define CP_COMMIT() asm volatile("cp.async.commit_group;")
#define CP_WAIT1() asm volatile("cp.async.wait_group 1;" ::: "memory")
#define CP_WAIT0() asm volatile("cp.async.wait_group 0;" ::: "memory")

// smem geometry for the wedge GEMM
#define ASTR 136                       // bf16 elems per row (272 B, conflict-free)
#define ATILE_B (128 * ASTR * 2)       // 34816 B per 128x128 bf16 tile
#define OFFA_HI 0
#define OFFA_LO ATILE_B
#define OFFB(buf) (2 * ATILE_B + (buf) * 2 * ATILE_B)
#define SMEM_WEDGE (6 * ATILE_B)       // 208896 B

// ---------------- zero fills -------------------------------------------------
__global__ void k_zero_deg(int N) {
    int i = blockIdx.x * blockDim.x + threadIdx.x;
    if (i < N) g_deg[i] = 0.f;
}
__global__ void k_zero_agg(int n) {
    int i = blockIdx.x * blockDim.x + threadIdx.x;
    if (i < n) g_agg[i] = 0.f;
}
__global__ void k_zero_readout(int B) {
    int i = blockIdx.x * blockDim.x + threadIdx.x;
    if (i < B * H) { g_hl[i] = 0.f; g_cl[i] = 0.f; }
    if (i < B * 2 * H) g_qstar[i] = 0.f;
}

// ---------------- weight prep ------------------------------------------------
__global__ void k_transpose_all(const float* __restrict__ rootW,
                                const float* __restrict__ gWih,
                                const float* __restrict__ gWhh,
                                const float* __restrict__ lWih,
                                const float* __restrict__ lWhh) {
    int i = blockIdx.x * blockDim.x + threadIdx.x;
    if (i < H * H)        { int r = i >> 6, c = i & 63;  g_rootWT[c * H + r]      = rootW[i]; }
    if (i < GRU3 * H)     { int r = i / H,  c = i % H;   g_gruWihT[c * GRU3 + r]  = gWih[i]; }
    if (i < GRU3 * H)     { int r = i / H,  c = i % H;   g_gruWhhT[c * GRU3 + r]  = gWhh[i]; }
    if (i < LST4 * 2 * H) { int r = i >> 7, c = i & 127; g_lstmWihT[c * LST4 + r] = lWih[i]; }
    if (i < LST4 * H)     { int r = i >> 6, c = i & 63;  g_lstmWhhT[c * LST4 + r] = lWhh[i]; }
}

__global__ void k_split_w2(const float* __restrict__ W2) {
    int i = blockIdx.x * blockDim.x + threadIdx.x;
    if (i < HH * WID) {
        float v = W2[i];
        __nv_bfloat16 h = __float2bfloat16(v);
        g_W2hi[i] = h;
        g_W2lo[i] = __float2bfloat16(v - __bfloat162float(h));
    }
}

// ---------------- node embedding ---------------------------------------------
__global__ void k_node_embed(const float* __restrict__ x, const float* __restrict__ W,
                             const float* __restrict__ b, int N) {
    int sub = threadIdx.x >> 6, o = threadIdx.x & 63;
    int n = blockIdx.x * 4 + sub;
    __shared__ float xs[4][11];
    bool ok = n < N;
    if (ok && o < 11) xs[sub][o] = x[n * 11 + o];
    __syncthreads();
    if (ok) {
        float a = b[o];
        #pragma unroll
        for (int i = 0; i < 11; i++) a += xs[sub][i] * W[o * 11 + i];
        g_x[n * H + o] = siluf(a);
    }
}

// ---------------- edge MLP hidden (split bf16) + degree ----------------------
__global__ void k_edge_hidden(const int* __restrict__ ei, const float* __restrict__ ea,
                              const float* __restrict__ pos, const float* __restrict__ W1,
                              const float* __restrict__ b1, int E) {
    int e = blockIdx.x, t = threadIdx.x;  // 128 threads
    __shared__ float ef[5];
    if (t < 4) ef[t] = ea[e * 4 + t];
    if (t == 4) {
        int s = ei[e], d = ei[E + e];
        float dx = pos[s * 3 + 0] - pos[d * 3 + 0];
        float dy = pos[s * 3 + 1] - pos[d * 3 + 1];
        float dz = pos[s * 3 + 2] - pos[d * 3 + 2];
        ef[4] = sqrtf(dx * dx + dy * dy + dz * dz);
    }
    if (t == 5) { int d = ei[E + e]; atomicAdd(&g_deg[d], 1.f); }
    __syncthreads();
    float a = b1[t];
    #pragma unroll
    for (int i = 0; i < 5; i++) a += ef[i] * W1[t * 5 + i];
    a = siluf(a);
    __nv_bfloat16 hb = __float2bfloat16(a);
    g_hidhi[(size_t)e * WID + t] = hb;
    g_hidlo[(size_t)e * WID + t] = __float2bfloat16(a - __bfloat162float(hb));
}

// ---------------- W_edge GEMM via mma.sync bf16 (3-product split) ------------
// D[128 e, 128 j] += hid[128,128] @ W2^T[128,128]; 32 j-iters per CTA.
__global__ __launch_bounds__(256, 1) void k_wedge_mma(const float* __restrict__ bias, int E) {
    extern __shared__ char smem[];
    uint32_t sb = smem_to_u32(smem);
    int tid = threadIdx.x, lane = tid & 31, wid = tid >> 5;
    int e0 = blockIdx.x * 128;

    // Load A tiles (hi+lo) with plain 16B loads
    #pragma unroll
    for (int q = 0; q < 16; q++) {
        int idx = q * 256 + tid;
        int tile = idx >> 11, rem = idx & 2047, r = rem >> 4, ch = rem & 15;
        const __nv_bfloat16* src = (tile ? g_hidlo : g_hidhi) + (size_t)(e0 + r) * WID + ch * 8;
        uint4 v = *(const uint4*)src;
        *(uint4*)(smem + (tile ? OFFA_LO : OFFA_HI) + r * 272 + ch * 16) = v;
    }
    // Preload B buffer 0 (j-block 0) via cp.async
    #pragma unroll
    for (int q = 0; q < 16; q++) {
        int idx = q * 256 + tid;
        int tile = idx >> 11, rem = idx & 2047, r = rem >> 4, ch = rem & 15;
        const __nv_bfloat16* g = (tile ? g_W2lo : g_W2hi) + (size_t)r * WID + ch * 8;
        uint32_t s = sb + OFFB(0) + tile * ATILE_B + r * 272 + ch * 16;
        CP_ASYNC16(s, g);
    }
    CP_COMMIT();

    int m0w = (wid >> 2) * 64, n0w = (wid & 3) * 32;
    // per-thread ldmatrix smem offsets (within a tile)
    uint32_t a_off = (uint32_t)(m0w + (lane & 15)) * 272 + (uint32_t)(lane >> 4) * 16;
    uint32_t b_off = (uint32_t)(n0w + (lane & 7)) * 272 + (uint32_t)((lane >> 3) & 1) * 16;

    for (int i = 0; i < 32; i++) {
        int cur = i & 1;
        if (i + 1 < 32) {
            int j1 = (i + 1) * 128;
            #pragma unroll
            for (int q = 0; q < 16; q++) {
                int idx = q * 256 + tid;
                int tile = idx >> 11, rem = idx & 2047, r = rem >> 4, ch = rem & 15;
                const __nv_bfloat16* g = (tile ? g_W2lo : g_W2hi) + (size_t)(j1 + r) * WID + ch * 8;
                uint32_t s = sb + OFFB((i + 1) & 1) + tile * ATILE_B + r * 272 + ch * 16;
                CP_ASYNC16(s, g);
            }
            CP_COMMIT();
            CP_WAIT1();
        } else {
            CP_WAIT0();
        }
        __syncthreads();

        float c[4][4][4];
        #pragma unroll
        for (int mf = 0; mf < 4; mf++)
            #pragma unroll
            for (int nf = 0; nf < 4; nf++) {
                c[mf][nf][0] = 0.f; c[mf][nf][1] = 0.f; c[mf][nf][2] = 0.f; c[mf][nf][3] = 0.f;
            }
        uint32_t aH = sb + OFFA_HI + a_off;
        uint32_t aL = sb + OFFA_LO + a_off;
        uint32_t bH = sb + OFFB(cur) + b_off;
        uint32_t bL = bH + ATILE_B;

        #pragma unroll
        for (int ks = 0; ks < 8; ks++) {
            uint32_t koff = (uint32_t)ks * 32;  // 16 bf16 = 32 bytes
            uint32_t ah[4][4], al[4][4], bh[4][2], bl[4][2];
            #pragma unroll
            for (int mf = 0; mf < 4; mf++) {
                uint32_t o = mf * (16 * 272) + koff;
                LDSM_X4(ah[mf], aH + o);
                LDSM_X4(al[mf], aL + o);
            }
            #pragma unroll
            for (int nf = 0; nf < 4; nf++) {
                uint32_t o = nf * (8 * 272) + koff;
                LDSM_X2(bh[nf], bH + o);
                LDSM_X2(bl[nf], bL + o);
            }
            #pragma unroll
            for (int mf = 0; mf < 4; mf++)
                #pragma unroll
                for (int nf = 0; nf < 4; nf++) {
                    MMA_BF16(c[mf][nf], ah[mf], bh[nf]);
                    MMA_BF16(c[mf][nf], ah[mf], bl[nf]);
                    MMA_BF16(c[mf][nf], al[mf], bh[nf]);
                }
        }

        // epilogue: add bias, convert fp16, store
        int j0 = i * 128;
        #pragma unroll
        for (int nf = 0; nf < 4; nf++) {
            int jc = n0w + nf * 8 + (lane & 3) * 2;
            float b0 = __ldg(&bias[j0 + jc]);
            float b1 = __ldg(&bias[j0 + jc + 1]);
            #pragma unroll
            for (int mf = 0; mf < 4; mf++) {
                int r0 = e0 + m0w + mf * 16 + (lane >> 2);
                if (r0 < E) {
                    __half2 h = __floats2half2_rn(c[mf][nf][0] + b0, c[mf][nf][1] + b1);
                    *(__half2*)(g_WedgeH + (size_t)r0 * HH + j0 + jc) = h;
                }
                int r1 = r0 + 8;
                if (r1 < E) {
                    __half2 h = __floats2half2_rn(c[mf][nf][2] + b0, c[mf][nf][3] + b1);
                    *(__half2*)(g_WedgeH + (size_t)r1 * HH + j0 + jc) = h;
                }
            }
        }
        __syncthreads();  // everyone done with B[cur] before next prefetch overwrites it
    }
}

// ---------------- message pass (fp16 W_edge): agg[dst] += x[src] @ W_e -------
__global__ void k_message(const int* __restrict__ ei, int E) {
    int w = threadIdx.x >> 5, lane = threadIdx.x & 31;
    int e = blockIdx.x * 8 + w;
    __shared__ float xs[8][H];
    if (e >= E) return;
    int s = ei[e], d = ei[E + e];
    xs[w][lane] = g_x[s * H + lane];
    xs[w][lane + 32] = g_x[s * H + 32 + lane];
    __syncwarp();
    const __half2* W = (const __half2*)g_WedgeH + (size_t)e * 2048 + lane;
    float a0 = 0.f, a1 = 0.f;
    #pragma unroll 8
    for (int i = 0; i < H; i++) {
        float2 wv = __half22float2(W[i * 32]);
        float xi = xs[w][i];
        a0 += xi * wv.x;
        a1 += xi * wv.y;
    }
    atomicAdd(&g_agg[d * H + 2 * lane], a0);
    atomicAdd(&g_agg[d * H + 2 * lane + 1], a1);
}

// ---------------- combine (root linear + agg/deg, silu) + GRU cell -----------
__global__ void k_combine_gru(const float* __restrict__ rb, const float* __restrict__ bih,
                              const float* __restrict__ bhh, int N) {
    int sub = threadIdx.x >> 6, o = threadIdx.x & 63;
    int n = blockIdx.x * 4 + sub;
    __shared__ float xs[4][H], xcs[4][H];
    bool ok = n < N;
    float xo = 0.f;
    if (ok) { xo = g_x[n * H + o]; xs[sub][o] = xo; }
    __syncthreads();
    if (ok) {
        float dg = g_deg[n]; if (dg < 1.f) dg = 1.f;
        float a = rb[o] + g_agg[n * H + o] / dg;
        #pragma unroll 8
        for (int i = 0; i < H; i++) a += xs[sub][i] * g_rootWT[i * H + o];
        xcs[sub][o] = siluf(a);
    }
    __syncthreads();
    if (ok) {
        float gi0 = bih[o], gi1 = bih[64 + o], gi2 = bih[128 + o];
        float gh0 = bhh[o], gh1 = bhh[64 + o], gh2 = bhh[128 + o];
        #pragma unroll 4
        for (int i = 0; i < H; i++) {
            float xi = xcs[sub][i], hi = xs[sub][i];
            const float* wi = &g_gruWihT[i * GRU3];
            const float* wh = &g_gruWhhT[i * GRU3];
            gi0 += xi * wi[o];       gh0 += hi * wh[o];
            gi1 += xi * wi[64 + o];  gh1 += hi * wh[64 + o];
            gi2 += xi * wi[128 + o]; gh2 += hi * wh[128 + o];
        }
        float r = sigm(gi0 + gh0);
        float z = sigm(gi1 + gh1);
        float nn = tanhf(gi2 + r * gh2);
        g_x[n * H + o] = (1.f - z) * nn + z * xo;
    }
}

// ---------------- Set2Set ----------------------------------------------------
__global__ void k_segptr(const int* __restrict__ batch, int N, int B) {
    int b = blockIdx.x * blockDim.x + threadIdx.x;
    if (b > B) return;
    int lo = 0, hi = N;
    while (lo < hi) { int m = (lo + hi) >> 1; if (batch[m] < b) lo = m + 1; else hi = m; }
    g_segptr[b] = lo;
}

__global__ void k_lstm(const float* __restrict__ bih, const float* __restrict__ bhh) {
    int b = blockIdx.x, t = threadIdx.x;  // 256 threads
    __shared__ float qs[2 * H], hs[H], gs[LST4];
    if (t < 2 * H) qs[t] = g_qstar[b * 2 * H + t];
    if (t < H) hs[t] = g_hl[b * H + t];
    __syncthreads();
    float g = bih[t] + bhh[t];
    #pragma unroll 8
    for (int i = 0; i < 2 * H; i++) g += qs[i] * g_lstmWihT[i * LST4 + t];
    #pragma unroll 8
    for (int i = 0; i < H; i++) g += hs[i] * g_lstmWhhT[i * LST4 + t];
    gs[t] = g;
    __syncthreads();
    if (t < H) {
        float ig = sigm(gs[t]), fg = sigm(gs[64 + t]);
        float gg = tanhf(gs[128 + t]), og = sigm(gs[192 + t]);
        float c = fg * g_cl[b * H + t] + ig * gg;
        g_cl[b * H + t] = c;
        g_hl[b * H + t] = og * tanhf(c);
    }
}

__global__ void k_escore(const int* __restrict__ batch, int N) {
    int gw = (blockIdx.x * blockDim.x + threadIdx.x) >> 5;
    int lane = threadIdx.x & 31;
    if (gw >= N) return;
    int b = batch[gw];
    float v = g_x[gw * H + lane] * g_hl[b * H + lane]
            + g_x[gw * H + 32 + lane] * g_hl[b * H + 32 + lane];
    #pragma unroll
    for (int off = 16; off; off >>= 1) v += __shfl_xor_sync(0xffffffffu, v, off);
    if (lane == 0) g_e[gw] = v;
}

__global__ void k_attend(int B) {
    int b = blockIdx.x, t = threadIdx.x;  // 64 threads
    __shared__ float red[H];
    int s = g_segptr[b], en = g_segptr[b + 1];
    float mx = -3.4e38f;
    for (int n = s + t; n < en; n += H) mx = fmaxf(mx, g_e[n]);
    red[t] = mx; __syncthreads();
    for (int off = 32; off; off >>= 1) { if (t < off) red[t] = fmaxf(red[t], red[t + off]); __syncthreads(); }
    float mxv = red[0];
    __syncthreads();
    float sm = 0.f;
    for (int n = s + t; n < en; n += H) sm += expf(g_e[n] - mxv);
    red[t] = sm; __syncthreads();
    for (int off = 32; off; off >>= 1) { if (t < off) red[t] += red[t + off]; __syncthreads(); }
    float den = red[0];
    float r = 0.f;
    for (int n = s; n < en; n++) r += expf(g_e[n] - mxv) * g_x[n * H + t];
    r = (en > s) ? r / den : 0.f;
    g_qstar[b * 2 * H + t] = g_hl[b * H + t];
    g_qstar[b * 2 * H + H + t] = r;
}

__global__ void k_out(const float* __restrict__ W1, const float* __restrict__ b1,
                      const float* __restrict__ W2, const float* __restrict__ b2,
                      float* __restrict__ out) {
    int b = blockIdx.x, t = threadIdx.x;  // 64 threads
    __shared__ float qs[2 * H];
    __shared__ float red[H];
    qs[t] = g_qstar[b * 2 * H + t];
    qs[64 + t] = g_qstar[b * 2 * H + 64 + t];
    __syncthreads();
    float a = b1[t];
    #pragma unroll 8
    for (int i = 0; i < 2 * H; i++) a += qs[i] * W1[t * 2 * H + i];
    red[t] = siluf(a) * W2[t];
    __syncthreads();
    for (int off = 32; off; off >>= 1) { if (t < off) red[t] += red[t + off]; __syncthreads(); }
    if (t == 0) out[b] = red[0] + b2[0];
}

// ---------------- host launcher ----------------------------------------------
extern "C" void kernel_launch(void* const* d_in, const int* in_sizes, int n_in,
                              void* d_out, int out_size) {
    const float* x = (const float*)d_in[0];
    int N = in_sizes[0] / 11;
    bool dictOrder = (in_sizes[2] == 3 * N);
    const int*   ei  = (const int*)  d_in[dictOrder ? 3 : 1];
    const float* ea  = (const float*)d_in[dictOrder ? 1 : 2];
    const float* pos = (const float*)d_in[dictOrder ? 2 : 3];
    const int*   batch = (const int*)d_in[4];
    int E = in_sizes[dictOrder ? 3 : 1] / 2;
    int B = out_size;

    const float* fl_W  = (const float*)d_in[5];
    const float* fl_b  = (const float*)d_in[6];
    const float* nn_W1 = (const float*)d_in[7];
    const float* nn_b1 = (const float*)d_in[8];
    const float* nn_W2 = (const float*)d_in[9];
    const float* nn_b2 = (const float*)d_in[10];
    const float* root_W = (const float*)d_in[11];
    const float* root_b = (const float*)d_in[12];
    const float* gru_Wih = (const float*)d_in[13];
    const float* gru_Whh = (const float*)d_in[14];
    const float* gru_bih = (const float*)d_in[15];
    const float* gru_bhh = (const float*)d_in[16];
    const float* lstm_Wih = (const float*)d_in[17];
    const float* lstm_Whh = (const float*)d_in[18];
    const float* lstm_bih = (const float*)d_in[19];
    const float* lstm_bhh = (const float*)d_in[20];
    const float* out_W1 = (const float*)d_in[21];
    const float* out_b1 = (const float*)d_in[22];
    const float* out_W2 = (const float*)d_in[23];
    const float* out_b2 = (const float*)d_in[24];
    float* out = (float*)d_out;

    cudaFuncSetAttribute(k_wedge_mma, cudaFuncAttributeMaxDynamicSharedMemorySize, SMEM_WEDGE);

    k_zero_deg<<<(N + 255) / 256, 256>>>(N);
    k_node_embed<<<(N + 3) / 4, 256>>>(x, fl_W, fl_b, N);
    k_edge_hidden<<<E, 128>>>(ei, ea, pos, nn_W1, nn_b1, E);
    k_split_w2<<<(HH * WID + 255) / 256, 256>>>(nn_W2);
    k_transpose_all<<<128, 256>>>(root_W, gru_Wih, gru_Whh, lstm_Wih, lstm_Whh);

    k_wedge_mma<<<(E + 127) / 128, 256, SMEM_WEDGE>>>(nn_b2, E);

    for (int l = 0; l < 4; l++) {
        k_zero_agg<<<(N * H + 255) / 256, 256>>>(N * H);
        k_message<<<(E + 7) / 8, 256>>>(ei, E);
        k_combine_gru<<<(N + 3) / 4, 256>>>(root_b, gru_bih, gru_bhh, N);
    }

    k_zero_readout<<<(B * 2 * H + 255) / 256, 256>>>(B);
    k_segptr<<<(B + 1 + 255) / 256, 256>>>(batch, N, B);
    for (int s = 0; s < 3; s++) {
        k_lstm<<<B, 256>>>(lstm_bih, lstm_bhh);
        k_escore<<<(N * 32 + 255) / 256, 256>>>(batch, N);
        k_attend<<<B, 64>>>(B);
    }
    k_out<<<B, 64>>>(out_W1, out_b1, out_W2, out_b2, out);
}

// round 4
// speedup vs baseline: 2.9775x; 1.4112x over previous
#include <cuda_runtime.h>
#include <cuda_fp16.h>
#include <math.h>
#include <stdint.h>

// ---------------- compile-time maxima (problem shapes are fixed) -------------
#define MAXN 10000
#define MAXE 50000
#define MAXB 512
#define H 64
#define HH 4096      // H*H
#define WID 128      // edge-MLP hidden width
#define GRU3 192     // 3*H
#define LST4 256     // 4*H

// ---------------- device scratch (allocation-free rule: __device__ globals) --
__device__ __half g_WedgeH[(size_t)MAXE * HH];        // 409.6 MB fp16 edge weights
__device__ __half g_hidH[(size_t)(MAXE + 128) * WID]; // edge MLP hidden fp16
__device__ __half g_W2H[HH * WID];                    // nn_W2 fp16
__device__ float g_x[MAXN * H];
__device__ float g_agg[MAXN * H];
__device__ float g_deg[MAXN];
__device__ float g_rootWT[H * H];
__device__ float g_gruWihT[H * GRU3];
__device__ float g_gruWhhT[H * GRU3];
__device__ float g_lstmWihT[2 * H * LST4];
__device__ float g_lstmWhhT[H * LST4];

__device__ __forceinline__ float sigm(float v) { return 1.f / (1.f + expf(-v)); }
__device__ __forceinline__ float siluf(float v) { return v / (1.f + expf(-v)); }

__device__ __forceinline__ uint32_t smem_to_u32(const void* p) {
    uint32_t a;
    asm("{ .reg .u64 t; cvta.to.shared.u64 t, %1; cvt.u32.u64 %0, t; }" : "=r"(a) : "l"(p));
    return a;
}

// ---------------- mma.sync helpers -------------------------------------------
#define LDSM_X4(r, addr) \
    asm volatile("ldmatrix.sync.aligned.m8n8.x4.shared.b16 {%0,%1,%2,%3}, [%4];" \
        : "=r"((r)[0]), "=r"((r)[1]), "=r"((r)[2]), "=r"((r)[3]) : "r"(addr))
#define LDSM_X2(r, addr) \
    asm volatile("ldmatrix.sync.aligned.m8n8.x2.shared.b16 {%0,%1}, [%2];" \
        : "=r"((r)[0]), "=r"((r)[1]) : "r"(addr))
#define MMA_F16(c, a, b) \
    asm volatile("mma.sync.aligned.m16n8k16.row.col.f32.f16.f16.f32 " \
        "{%0,%1,%2,%3}, {%4,%5,%6,%7}, {%8,%9}, {%0,%1,%2,%3};" \
        : "+f"((c)[0]), "+f"((c)[1]), "+f"((c)[2]), "+f"((c)[3]) \
        : "r"((a)[0]), "r"((a)[1]), "r"((a)[2]), "r"((a)[3]), "r"((b)[0]), "r"((b)[1]))
#define CP_ASYNC16(s, g) \
    asm volatile("cp.async.cg.shared.global [%0], [%1], 16;" :: "r"(s), "l"(g))
#define CP_COMMIT() asm volatile("cp.async.commit_group;")
#define CP_WAIT1() asm volatile("cp.async.wait_group 1;" ::: "memory")
#define CP_WAIT0() asm volatile("cp.async.wait_group 0;" ::: "memory")

// smem geometry for the wedge GEMM (fp16, single product)
#define ATILE_B (128 * 136 * 2)        // 34816 B per 128x128 fp16 tile (272 B rows)
#define OFFA 0
#define OFFB(buf) (ATILE_B + (buf) * ATILE_B)
#define SMEM_WEDGE (3 * ATILE_B)       // 104448 B -> 2 CTAs/SM

// ---------------- zero fill (agg, once) --------------------------------------
__global__ void k_zero_agg(int n) {
    int i = blockIdx.x * blockDim.x + threadIdx.x;
    if (i < n) g_agg[i] = 0.f;
}

// ---------------- weight prep: fp16 W2 + transposes --------------------------
__global__ void k_prep(const float* __restrict__ W2,
                       const float* __restrict__ rootW,
                       const float* __restrict__ gWih,
                       const float* __restrict__ gWhh,
                       const float* __restrict__ lWih,
                       const float* __restrict__ lWhh) {
    int i = blockIdx.x * blockDim.x + threadIdx.x;
    if (i < HH * WID) g_W2H[i] = __float2half(W2[i]);
    if (i < H * H)        { int r = i >> 6, c = i & 63;  g_rootWT[c * H + r]      = rootW[i]; }
    if (i < GRU3 * H)     { int r = i / H,  c = i % H;   g_gruWihT[c * GRU3 + r]  = gWih[i]; }
    if (i < GRU3 * H)     { int r = i / H,  c = i % H;   g_gruWhhT[c * GRU3 + r]  = gWhh[i]; }
    if (i < LST4 * 2 * H) { int r = i >> 7, c = i & 127; g_lstmWihT[c * LST4 + r] = lWih[i]; }
    if (i < LST4 * H)     { int r = i >> 6, c = i & 63;  g_lstmWhhT[c * LST4 + r] = lWhh[i]; }
}

// ---------------- node embedding (also zeroes deg) ---------------------------
__global__ void k_node_embed(const float* __restrict__ x, const float* __restrict__ W,
                             const float* __restrict__ b, int N) {
    int sub = threadIdx.x >> 6, o = threadIdx.x & 63;
    int n = blockIdx.x * 4 + sub;
    __shared__ float xs[4][11];
    bool ok = n < N;
    if (ok && o < 11) xs[sub][o] = x[n * 11 + o];
    if (ok && o == 0) g_deg[n] = 0.f;
    __syncthreads();
    if (ok) {
        float a = b[o];
        #pragma unroll
        for (int i = 0; i < 11; i++) a += xs[sub][i] * W[o * 11 + i];
        g_x[n * H + o] = siluf(a);
    }
}

// ---------------- edge MLP hidden (fp16) + degree ----------------------------
__global__ void k_edge_hidden(const int* __restrict__ ei, const float* __restrict__ ea,
                              const float* __restrict__ pos, const float* __restrict__ W1,
                              const float* __restrict__ b1, int E) {
    int e = blockIdx.x, t = threadIdx.x;  // 128 threads
    __shared__ float ef[5];
    if (t < 4) ef[t] = ea[e * 4 + t];
    if (t == 4) {
        int s = ei[e], d = ei[E + e];
        float dx = pos[s * 3 + 0] - pos[d * 3 + 0];
        float dy = pos[s * 3 + 1] - pos[d * 3 + 1];
        float dz = pos[s * 3 + 2] - pos[d * 3 + 2];
        ef[4] = sqrtf(dx * dx + dy * dy + dz * dz);
    }
    if (t == 5) { int d = ei[E + e]; atomicAdd(&g_deg[d], 1.f); }
    __syncthreads();
    float a = b1[t];
    #pragma unroll
    for (int i = 0; i < 5; i++) a += ef[i] * W1[t * 5 + i];
    g_hidH[(size_t)e * WID + t] = __float2half(siluf(a));
}

// ---------------- W_edge GEMM via mma.sync fp16 (single product) -------------
// D[128 e, 128 j] = hid[128,128] @ W2^T[128,128]; 32 j-iters per CTA.
__global__ __launch_bounds__(256, 2) void k_wedge_mma(const float* __restrict__ bias, int E) {
    extern __shared__ char smem[];
    uint32_t sb = smem_to_u32(smem);
    int tid = threadIdx.x, lane = tid & 31, wid = tid >> 5;
    int e0 = blockIdx.x * 128;

    // Load A tile (128 rows x 128 halves)
    #pragma unroll
    for (int q = 0; q < 8; q++) {
        int idx = q * 256 + tid;
        int r = idx >> 4, ch = idx & 15;
        uint4 v = *(const uint4*)(g_hidH + (size_t)(e0 + r) * WID + ch * 8);
        *(uint4*)(smem + OFFA + r * 272 + ch * 16) = v;
    }
    // Preload B buffer 0 (j-block 0) via cp.async
    #pragma unroll
    for (int q = 0; q < 8; q++) {
        int idx = q * 256 + tid;
        int r = idx >> 4, ch = idx & 15;
        CP_ASYNC16(sb + OFFB(0) + r * 272 + ch * 16,
                   g_W2H + (size_t)r * WID + ch * 8);
    }
    CP_COMMIT();

    int m0w = (wid >> 2) * 64, n0w = (wid & 3) * 32;
    uint32_t a_off = (uint32_t)(m0w + (lane & 15)) * 272 + (uint32_t)(lane >> 4) * 16;
    uint32_t b_off = (uint32_t)(n0w + (lane & 7)) * 272 + (uint32_t)((lane >> 3) & 1) * 16;

    for (int i = 0; i < 32; i++) {
        int cur = i & 1;
        if (i + 1 < 32) {
            int j1 = (i + 1) * 128;
            #pragma unroll
            for (int q = 0; q < 8; q++) {
                int idx = q * 256 + tid;
                int r = idx >> 4, ch = idx & 15;
                CP_ASYNC16(sb + OFFB((i + 1) & 1) + r * 272 + ch * 16,
                           g_W2H + (size_t)(j1 + r) * WID + ch * 8);
            }
            CP_COMMIT();
            CP_WAIT1();
        } else {
            CP_WAIT0();
        }
        __syncthreads();

        float c[4][4][4];
        #pragma unroll
        for (int mf = 0; mf < 4; mf++)
            #pragma unroll
            for (int nf = 0; nf < 4; nf++) {
                c[mf][nf][0] = 0.f; c[mf][nf][1] = 0.f; c[mf][nf][2] = 0.f; c[mf][nf][3] = 0.f;
            }
        uint32_t aB = sb + OFFA + a_off;
        uint32_t bB = sb + OFFB(cur) + b_off;

        #pragma unroll
        for (int ks = 0; ks < 8; ks++) {
            uint32_t koff = (uint32_t)ks * 32;  // 16 halves = 32 bytes
            uint32_t af[4][4], bf[4][2];
            #pragma unroll
            for (int mf = 0; mf < 4; mf++) LDSM_X4(af[mf], aB + mf * (16 * 272) + koff);
            #pragma unroll
            for (int nf = 0; nf < 4; nf++) LDSM_X2(bf[nf], bB + nf * (8 * 272) + koff);
            #pragma unroll
            for (int mf = 0; mf < 4; mf++)
                #pragma unroll
                for (int nf = 0; nf < 4; nf++) MMA_F16(c[mf][nf], af[mf], bf[nf]);
        }

        // epilogue: add bias, convert fp16, store
        int j0 = i * 128;
        #pragma unroll
        for (int nf = 0; nf < 4; nf++) {
            int jc = n0w + nf * 8 + (lane & 3) * 2;
            float b0 = __ldg(&bias[j0 + jc]);
            float b1 = __ldg(&bias[j0 + jc + 1]);
            #pragma unroll
            for (int mf = 0; mf < 4; mf++) {
                int r0 = e0 + m0w + mf * 16 + (lane >> 2);
                if (r0 < E) {
                    __half2 h = __floats2half2_rn(c[mf][nf][0] + b0, c[mf][nf][1] + b1);
                    *(__half2*)(g_WedgeH + (size_t)r0 * HH + j0 + jc) = h;
                }
                int r1 = r0 + 8;
                if (r1 < E) {
                    __half2 h = __floats2half2_rn(c[mf][nf][2] + b0, c[mf][nf][3] + b1);
                    *(__half2*)(g_WedgeH + (size_t)r1 * HH + j0 + jc) = h;
                }
            }
        }
        __syncthreads();  // all warps done with B[cur] before next prefetch lands
    }
}

// ---------------- message pass (fp16 W_edge): agg[dst] += x[src] @ W_e -------
__global__ void k_message(const int* __restrict__ ei, int E) {
    int w = threadIdx.x >> 5, lane = threadIdx.x & 31;
    int e = blockIdx.x * 8 + w;
    __shared__ float xs[8][H];
    if (e >= E) return;
    int s = ei[e], d = ei[E + e];
    xs[w][lane] = g_x[s * H + lane];
    xs[w][lane + 32] = g_x[s * H + 32 + lane];
    __syncwarp();
    const __half2* W = (const __half2*)g_WedgeH + (size_t)e * 2048 + lane;
    float a0 = 0.f, a1 = 0.f;
    #pragma unroll 8
    for (int i = 0; i < H; i++) {
        float2 wv = __half22float2(W[i * 32]);
        float xi = xs[w][i];
        a0 += xi * wv.x;
        a1 += xi * wv.y;
    }
    atomicAdd(&g_agg[d * H + 2 * lane], a0);
    atomicAdd(&g_agg[d * H + 2 * lane + 1], a1);
}

// ---------------- combine + GRU cell (resets agg for next layer) -------------
__global__ void k_combine_gru(const float* __restrict__ rb, const float* __restrict__ bih,
                              const float* __restrict__ bhh, int N) {
    int sub = threadIdx.x >> 6, o = threadIdx.x & 63;
    int n = blockIdx.x * 4 + sub;
    __shared__ float xs[4][H], xcs[4][H];
    bool ok = n < N;
    float xo = 0.f;
    if (ok) { xo = g_x[n * H + o]; xs[sub][o] = xo; }
    __syncthreads();
    if (ok) {
        float dg = g_deg[n]; if (dg < 1.f) dg = 1.f;
        float a = rb[o] + g_agg[n * H + o] / dg;
        g_agg[n * H + o] = 0.f;  // reset for next layer's atomics
        #pragma unroll 8
        for (int i = 0; i < H; i++) a += xs[sub][i] * g_rootWT[i * H + o];
        xcs[sub][o] = siluf(a);
    }
    __syncthreads();
    if (ok) {
        float gi0 = bih[o], gi1 = bih[64 + o], gi2 = bih[128 + o];
        float gh0 = bhh[o], gh1 = bhh[64 + o], gh2 = bhh[128 + o];
        #pragma unroll 4
        for (int i = 0; i < H; i++) {
            float xi = xcs[sub][i], hi = xs[sub][i];
            const float* wi = &g_gruWihT[i * GRU3];
            const float* wh = &g_gruWhhT[i * GRU3];
            gi0 += xi * wi[o];       gh0 += hi * wh[o];
            gi1 += xi * wi[64 + o];  gh1 += hi * wh[64 + o];
            gi2 += xi * wi[128 + o]; gh2 += hi * wh[128 + o];
        }
        float r = sigm(gi0 + gh0);
        float z = sigm(gi1 + gh1);
        float nn = tanhf(gi2 + r * gh2);
        g_x[n * H + o] = (1.f - z) * nn + z * xo;
    }
}

// ---------------- fused Set2Set readout + output head (1 block per graph) ----
__global__ __launch_bounds__(256) void k_readout(
        const int* __restrict__ batch,
        const float* __restrict__ lbih, const float* __restrict__ lbhh,
        const float* __restrict__ oW1, const float* __restrict__ ob1,
        const float* __restrict__ oW2, const float* __restrict__ ob2,
        float* __restrict__ out, int N) {
    int b = blockIdx.x, t = threadIdx.x;  // 256 threads
    __shared__ float qs[128], hs[64], cs[64], gs[256], red[256];
    __shared__ float ea[1024];
    __shared__ int sseg[2];
    if (t < 2) {
        int target = b + t;
        int lo = 0, hi = N;
        while (lo < hi) { int m = (lo + hi) >> 1; if (batch[m] < target) lo = m + 1; else hi = m; }
        sseg[t] = lo;
    }
    if (t < 128) qs[t] = 0.f;
    if (t < 64) { hs[t] = 0.f; cs[t] = 0.f; }
    __syncthreads();
    int s = sseg[0], en = sseg[1], cnt = en - s;

    for (int step = 0; step < 3; step++) {
        // LSTM cell: 256 gates, one per thread
        float g = lbih[t] + lbhh[t];
        #pragma unroll 8
        for (int i = 0; i < 128; i++) g += qs[i] * g_lstmWihT[i * LST4 + t];
        #pragma unroll 8
        for (int i = 0; i < 64; i++)  g += hs[i] * g_lstmWhhT[i * LST4 + t];
        gs[t] = g;
        __syncthreads();
        if (t < 64) {
            float ig = sigm(gs[t]), fg = sigm(gs[64 + t]);
            float gg = tanhf(gs[128 + t]), og = sigm(gs[192 + t]);
            float c = fg * cs[t] + ig * gg;
            cs[t] = c;
            hs[t] = og * tanhf(c);
        }
        __syncthreads();
        // attention scores: one warp per node
        int w = t >> 5, lane = t & 31;
        for (int n = s + w; n < en; n += 8) {
            float v = g_x[n * 64 + lane] * hs[lane] + g_x[n * 64 + 32 + lane] * hs[32 + lane];
            #pragma unroll
            for (int off = 16; off; off >>= 1) v += __shfl_xor_sync(0xffffffffu, v, off);
            if (lane == 0) ea[n - s] = v;
        }
        __syncthreads();
        // softmax over segment
        float mx = -3.4e38f;
        for (int n = t; n < cnt; n += 256) mx = fmaxf(mx, ea[n]);
        red[t] = mx; __syncthreads();
        for (int off = 128; off; off >>= 1) { if (t < off) red[t] = fmaxf(red[t], red[t + off]); __syncthreads(); }
        mx = red[0]; __syncthreads();
        float sm = 0.f;
        for (int n = t; n < cnt; n += 256) { float av = expf(ea[n] - mx); ea[n] = av; sm += av; }
        red[t] = sm; __syncthreads();
        for (int off = 128; off; off >>= 1) { if (t < off) red[t] += red[t + off]; __syncthreads(); }
        float den = red[0];
        __syncthreads();
        // weighted readout + q_star update
        if (t < 64) {
            float r = 0.f;
            for (int n = 0; n < cnt; n++) r += ea[n] * g_x[(s + n) * 64 + t];
            qs[64 + t] = (cnt > 0) ? r / den : 0.f;
            qs[t] = hs[t];
        }
        __syncthreads();
    }
    // output head: silu(q_star @ W1^T + b1) @ W2^T + b2
    if (t < 64) {
        float a = ob1[t];
        #pragma unroll 8
        for (int i = 0; i < 128; i++) a += qs[i] * oW1[t * 128 + i];
        red[t] = siluf(a) * oW2[t];
    }
    __syncthreads();
    if (t < 32) {
        float v = red[t] + red[t + 32];
        #pragma unroll
        for (int off = 16; off; off >>= 1) v += __shfl_xor_sync(0xffffffffu, v, off);
        if (t == 0) out[b] = v + ob2[0];
    }
}

// ---------------- host launcher ----------------------------------------------
extern "C" void kernel_launch(void* const* d_in, const int* in_sizes, int n_in,
                              void* d_out, int out_size) {
    const float* x = (const float*)d_in[0];
    int N = in_sizes[0] / 11;
    bool dictOrder = (in_sizes[2] == 3 * N);
    const int*   ei  = (const int*)  d_in[dictOrder ? 3 : 1];
    const float* ea  = (const float*)d_in[dictOrder ? 1 : 2];
    const float* pos = (const float*)d_in[dictOrder ? 2 : 3];
    const int*   batch = (const int*)d_in[4];
    int E = in_sizes[dictOrder ? 3 : 1] / 2;
    int B = out_size;

    const float* fl_W  = (const float*)d_in[5];
    const float* fl_b  = (const float*)d_in[6];
    const float* nn_W1 = (const float*)d_in[7];
    const float* nn_b1 = (const float*)d_in[8];
    const float* nn_W2 = (const float*)d_in[9];
    const float* nn_b2 = (const float*)d_in[10];
    const float* root_W = (const float*)d_in[11];
    const float* root_b = (const float*)d_in[12];
    const float* gru_Wih = (const float*)d_in[13];
    const float* gru_Whh = (const float*)d_in[14];
    const float* gru_bih = (const float*)d_in[15];
    const float* gru_bhh = (const float*)d_in[16];
    const float* lstm_Wih = (const float*)d_in[17];
    const float* lstm_Whh = (const float*)d_in[18];
    const float* lstm_bih = (const float*)d_in[19];
    const float* lstm_bhh = (const float*)d_in[20];
    const float* out_W1 = (const float*)d_in[21];
    const float* out_b1 = (const float*)d_in[22];
    const float* out_W2 = (const float*)d_in[23];
    const float* out_b2 = (const float*)d_in[24];
    float* out = (float*)d_out;

    cudaFuncSetAttribute(k_wedge_mma, cudaFuncAttributeMaxDynamicSharedMemorySize, SMEM_WEDGE);

    k_node_embed<<<(N + 3) / 4, 256>>>(x, fl_W, fl_b, N);
    k_edge_hidden<<<E, 128>>>(ei, ea, pos, nn_W1, nn_b1, E);
    k_prep<<<(HH * WID + 255) / 256, 256>>>(nn_W2, root_W, gru_Wih, gru_Whh, lstm_Wih, lstm_Whh);
    k_zero_agg<<<(N * H + 255) / 256, 256>>>(N * H);

    k_wedge_mma<<<(E + 127) / 128, 256, SMEM_WEDGE>>>(nn_b2, E);

    for (int l = 0; l < 4; l++) {
        k_message<<<(E + 7) / 8, 256>>>(ei, E);
        k_combine_gru<<<(N + 3) / 4, 256>>>(root_b, gru_bih, gru_bhh, N);
    }

    k_readout<<<B, 256>>>(batch, lstm_bih, lstm_bhh, out_W1, out_b1, out_W2, out_b2, out, N);
}